// round 10
// baseline (speedup 1.0000x reference)
#include <cuda_runtime.h>
#include <cuda_bf16.h>
#include <math.h>
#include <stdint.h>

// Problem constants (fixed shapes)
#define T_STEPS 2048
#define BATCH   256
#define HID     256
#define OUT_DIM 16

// Scratch (device globals: allocation-free kernel_launch)
__device__ float g_xp[134217728];          // [T][B][H] fp32, 512 MB
__device__ float g_hfinal[BATCH * HID];
__device__ __nv_bfloat16 g_xhi[134217728]; // x hi split, 256 MB
__device__ __nv_bfloat16 g_xlo[134217728]; // x lo split, 256 MB
__device__ __nv_bfloat16 g_WThi[65536];    // W_ih^T hi: [n][k]
__device__ __nv_bfloat16 g_WTlo[65536];    // W_ih^T lo: [n][k]

// ---------------------------------------------------------------------------
// helpers
// ---------------------------------------------------------------------------
__device__ __forceinline__ uint32_t smem_u32(const void* p) {
    uint32_t a;
    asm("{ .reg .u64 t; cvta.to.shared.u64 t, %1; cvt.u32.u64 %0, t; }"
        : "=r"(a) : "l"(p));
    return a;
}
__device__ __forceinline__ void cp16(uint32_t dst, const void* src) {
    asm volatile("cp.async.cg.shared.global [%0], [%1], 16;"
                 :: "r"(dst), "l"(src) : "memory");
}
__device__ __forceinline__ void ldsm_x4(uint32_t* r, uint32_t addr) {
    asm volatile("ldmatrix.sync.aligned.m8n8.x4.shared.b16 {%0,%1,%2,%3}, [%4];"
                 : "=r"(r[0]), "=r"(r[1]), "=r"(r[2]), "=r"(r[3]) : "r"(addr));
}
__device__ __forceinline__ void ldsm_x2(uint32_t* r, uint32_t addr) {
    asm volatile("ldmatrix.sync.aligned.m8n8.x2.shared.b16 {%0,%1}, [%2];"
                 : "=r"(r[0]), "=r"(r[1]) : "r"(addr));
}
__device__ __forceinline__ void mma_bf16(float* c, const uint32_t* a, const uint32_t* b) {
    asm volatile(
        "mma.sync.aligned.m16n8k16.row.col.f32.bf16.bf16.f32 "
        "{%0,%1,%2,%3}, {%4,%5,%6,%7}, {%8,%9}, {%0,%1,%2,%3};"
        : "+f"(c[0]), "+f"(c[1]), "+f"(c[2]), "+f"(c[3])
        : "r"(a[0]), "r"(a[1]), "r"(a[2]), "r"(a[3]), "r"(b[0]), "r"(b[1]));
}

// f32x2 helpers
__device__ __forceinline__ unsigned long long f32x2_pack(float x, float y) {
    unsigned long long r;
    asm("mov.b64 %0, {%1, %2};" : "=l"(r) : "r"(__float_as_uint(x)), "r"(__float_as_uint(y)));
    return r;
}
__device__ __forceinline__ void f32x2_unpack(unsigned long long v, float& x, float& y) {
    unsigned int lo, hi;
    asm("mov.b64 {%0, %1}, %2;" : "=r"(lo), "=r"(hi) : "l"(v));
    x = __uint_as_float(lo);
    y = __uint_as_float(hi);
}
__device__ __forceinline__ void ffma2(unsigned long long& acc,
                                      unsigned long long a, unsigned long long b) {
    asm("fma.rn.f32x2 %0, %1, %2, %0;" : "+l"(acc) : "l"(a), "l"(b));
}
__device__ __forceinline__ void fadd2(unsigned long long& acc, unsigned long long b) {
    asm("add.rn.f32x2 %0, %0, %1;" : "+l"(acc) : "l"(b));
}

// cluster helpers
__device__ __forceinline__ uint32_t ctarank() {
    uint32_t r;
    asm("mov.u32 %0, %%cluster_ctarank;" : "=r"(r));
    return r;
}
__device__ __forceinline__ uint32_t mapa_peer(uint32_t laddr, uint32_t rank) {
    uint32_t r;
    asm("mapa.shared::cluster.u32 %0, %1, %2;" : "=r"(r) : "r"(laddr), "r"(rank));
    return r;
}
__device__ __forceinline__ void st_cluster_u64(uint32_t raddr, unsigned long long v) {
    asm volatile("st.shared::cluster.b64 [%0], %1;" :: "r"(raddr), "l"(v) : "memory");
}

// ---------------------------------------------------------------------------
// Kernel 0a: W_ih [k][n] -> transposed bf16 hi/lo [n][k]
// ---------------------------------------------------------------------------
__global__ __launch_bounds__(256)
void prep_w_kernel(const float* __restrict__ Wih) {
    int n = blockIdx.x;
    int k = threadIdx.x;
    float w = Wih[k * 256 + n];
    __nv_bfloat16 hi = __float2bfloat16(w);
    float lof = w - __bfloat162float(hi);
    g_WThi[n * 256 + k] = hi;
    g_WTlo[n * 256 + k] = __float2bfloat16(lof);
}

// ---------------------------------------------------------------------------
// Kernel 0b: x fp32 -> bf16 hi/lo splits (streaming)
// ---------------------------------------------------------------------------
__global__ __launch_bounds__(256)
void prep_x_kernel(const float* __restrict__ x) {
    size_t i = ((size_t)blockIdx.x * 256 + threadIdx.x) * 4;
    float4 f = *(const float4*)&x[i];
    __nv_bfloat162 h0 = __float22bfloat162_rn(make_float2(f.x, f.y));
    __nv_bfloat162 h1 = __float22bfloat162_rn(make_float2(f.z, f.w));
    float2 l0 = make_float2(f.x - __bfloat162float(h0.x), f.y - __bfloat162float(h0.y));
    float2 l1 = make_float2(f.z - __bfloat162float(h1.x), f.w - __bfloat162float(h1.y));
    __nv_bfloat162 lo0 = __float22bfloat162_rn(l0);
    __nv_bfloat162 lo1 = __float22bfloat162_rn(l1);
    uint2 hv, lv;
    hv.x = *(uint32_t*)&h0; hv.y = *(uint32_t*)&h1;
    lv.x = *(uint32_t*)&lo0; lv.y = *(uint32_t*)&lo1;
    *(uint2*)&g_xhi[i] = hv;
    *(uint2*)&g_xlo[i] = lv;
}

// ---------------------------------------------------------------------------
// Kernel 1: mma.sync bf16-split GEMM (unchanged from R5 passing version)
// ---------------------------------------------------------------------------
#define PADROW   40
#define AHI_OFF  0
#define ALO_OFF  10240
#define BHI_OFF  20480
#define BLO_OFF  40960
#define STAGE_B  61440
#define GSMEM    (2 * STAGE_B)

__global__ __launch_bounds__(512, 1)
void gemm_xp_mma_kernel(const float* __restrict__ bh) {
    extern __shared__ __align__(16) char dsm[];
    __shared__ float bias_s[256];

    const int tid = threadIdx.x;
    const int wid = tid >> 5;
    const int lid = tid & 31;
    const int wm  = wid & 1;
    const int wn  = wid >> 1;
    const uint32_t sb = smem_u32(dsm);

    if (tid < 256) bias_s[tid] = bh[tid];

    const size_t r0 = (size_t)blockIdx.x * 128;

    auto fill = [&](int s, int kt) {
        uint32_t base = sb + s * STAGE_B;
        {
            int c = tid;
            int row = c >> 2, q = c & 3;
            size_t ga = (r0 + row) * 256 + kt + q * 8;
            uint32_t d = base + row * (PADROW * 2) + q * 16;
            cp16(d + AHI_OFF, g_xhi + ga);
            cp16(d + ALO_OFF, g_xlo + ga);
        }
#pragma unroll
        for (int i = 0; i < 2; i++) {
            int c = tid + i * 512;
            int row = c >> 2, q = c & 3;
            size_t gb = (size_t)row * 256 + kt + q * 8;
            uint32_t d = base + row * (PADROW * 2) + q * 16;
            cp16(d + BHI_OFF, g_WThi + gb);
            cp16(d + BLO_OFF, g_WTlo + gb);
        }
    };

    float acc[4][4][4];
#pragma unroll
    for (int mi = 0; mi < 4; mi++)
#pragma unroll
        for (int ni = 0; ni < 4; ni++)
#pragma unroll
            for (int e = 0; e < 4; e++) acc[mi][ni][e] = 0.f;

    fill(0, 0);
    asm volatile("cp.async.commit_group;" ::: "memory");
    fill(1, 32);
    asm volatile("cp.async.commit_group;" ::: "memory");

    const int arow  = wm * 64 + (lid & 15);
    const int acolb = (lid >> 4) * 16;
    const int bnrow = wn * 32 + (lid & 7);
    const int bkoff = ((lid >> 3) & 1) * 16;

    for (int it = 0; it < 8; it++) {
        asm volatile("cp.async.wait_group 1;" ::: "memory");
        __syncthreads();

        uint32_t As = sb + (it & 1) * STAGE_B;
        uint32_t Bs = As + BHI_OFF;

#pragma unroll
        for (int k16 = 0; k16 < 2; k16++) {
            uint32_t ahi[4][4], alo[4][4];
#pragma unroll
            for (int mi = 0; mi < 4; mi++) {
                uint32_t a = As + (arow + mi * 16) * (PADROW * 2) + k16 * 32 + acolb;
                ldsm_x4(ahi[mi], a + AHI_OFF);
                ldsm_x4(alo[mi], a + ALO_OFF);
            }
#pragma unroll
            for (int ni = 0; ni < 4; ni++) {
                uint32_t bhi[2], blo[2];
                uint32_t ba = Bs + (bnrow + ni * 8) * (PADROW * 2) + k16 * 32 + bkoff;
                ldsm_x2(bhi, ba);
                ldsm_x2(blo, ba + (BLO_OFF - BHI_OFF));
#pragma unroll
                for (int mi = 0; mi < 4; mi++) {
                    mma_bf16(acc[mi][ni], ahi[mi], bhi);
                    mma_bf16(acc[mi][ni], alo[mi], bhi);
                    mma_bf16(acc[mi][ni], ahi[mi], blo);
                }
            }
        }
        __syncthreads();
        if (it + 2 < 8) fill(it & 1, (it + 2) * 32);
        asm volatile("cp.async.commit_group;" ::: "memory");
    }

#pragma unroll
    for (int mi = 0; mi < 4; mi++) {
#pragma unroll
        for (int ni = 0; ni < 4; ni++) {
            int m = wm * 64 + mi * 16 + (lid >> 2);
            int n = wn * 32 + ni * 8 + (lid & 3) * 2;
            float b0 = bias_s[n], b1 = bias_s[n + 1];
            {
                size_t r = r0 + m;
                int t = (int)(r & 2047), b = (int)(r >> 11);
                float2 v = make_float2(acc[mi][ni][0] + b0, acc[mi][ni][1] + b1);
                *(float2*)&g_xp[((size_t)t * BATCH + b) * HID + n] = v;
            }
            {
                size_t r = r0 + m + 8;
                int t = (int)(r & 2047), b = (int)(r >> 11);
                float2 v = make_float2(acc[mi][ni][2] + b0, acc[mi][ni][3] + b1);
                *(float2*)&g_xp[((size_t)t * BATCH + b) * HID + n] = v;
            }
        }
    }
}

// ---------------------------------------------------------------------------
// Kernel 2: 2-CTA-cluster recurrence, W entirely in registers.
// 64 clusters x 2 CTAs (128 CTAs) x 256 threads. Cluster c owns batches
// 4c..4c+3. CTA rank r owns k in [r*128, r*128+128) AND finalizes h columns
// [r*128, r*128+128) (j-split == k-split -> h never crosses CTAs).
// Thread j (global col = kb + ... actually tid is global col) holds W rows
// [kb, kb+128) of its column in 64 u64 registers. Per step:
//   1. k-loop: 4-batch partials from h broadcasts (smem) x W (regs)
//   2. publish partials: local cols -> own X slot0; peer cols -> peer X
//      slot1 via DSMEM (st.shared::cluster)
//   3. __syncthreads; thread0: release-cluster mbarrier arrive on peer
//   4. all wait own mbarrier (parity), finalize 2 outputs/thread, tanh,
//      store h locally; __syncthreads.
// ---------------------------------------------------------------------------
__global__ __launch_bounds__(256, 1) __cluster_dims__(2, 1, 1)
void rnn_recurrence_kernel(const float* __restrict__ W_hh) {
    __shared__ __align__(16) float hsm[4][128];      // h for my k/j-range, 4 batches
    __shared__ __align__(16) float X[2][2][128][4];  // [parity][slot][col][batch]
    __shared__ __align__(8) unsigned long long mbar;

    const int tid  = threadIdx.x;
    const uint32_t rank = ctarank();
    const int kb   = (int)rank * 128;
    const int b0c  = (blockIdx.x >> 1) * 4;   // first batch of this cluster
    const int j    = tid;                      // global column owned for partials

    // --- W rows [kb, kb+128) of column j -> 64 u64 k-pair registers ---
    unsigned long long wreg[64];
#pragma unroll
    for (int r = 0; r < 64; r++)
        wreg[r] = f32x2_pack(W_hh[(kb + 2 * r) * 256 + j],
                             W_hh[(kb + 2 * r + 1) * 256 + j]);

    // --- init h = 0, mbarrier ---
    for (int e = tid; e < 512; e += 256) ((float*)hsm)[e] = 0.f;
    if (tid == 0) {
        asm volatile("mbarrier.init.shared.b64 [%0], 1;"
                     :: "r"(smem_u32(&mbar)) : "memory");
    }
    __syncthreads();
    // cluster-wide: mbarriers initialized before any remote arrive
    asm volatile("barrier.cluster.arrive.aligned;" ::: "memory");
    asm volatile("barrier.cluster.wait.aligned;" ::: "memory");

    // finalize role: column kb + fcol, batches b0c + bb, b0c + bb + 1
    const int fcol = tid & 127;
    const int bb   = (tid >> 7) * 2;
    const float* xpp = g_xp + (size_t)(b0c + bb) * HID + kb + fcol;
    float p0 = xpp[0];
    float p1 = xpp[HID];

    // publish targets (constant across steps)
    const int jl_local  = j - kb;              // valid if local
    const int jl_remote = j - (128 - kb);      // col index in peer's range
    const bool is_local = (j >= kb) && (j < kb + 128);
    const uint32_t mbar_peer = mapa_peer(smem_u32(&mbar), rank ^ 1);

    const uint32_t mymbar = smem_u32(&mbar);
    float h0v = 0.f, h1v = 0.f;

    for (int t = 0; t < T_STEPS; t++) {
        const int par = t & 1;

        // 8 chains: acc[batch][0/1]
        unsigned long long a00 = 0, a01 = 0, a10 = 0, a11 = 0;
        unsigned long long a20 = 0, a21 = 0, a30 = 0, a31 = 0;

        int tn = (t + 1 < T_STEPS) ? (t + 1) : t;
        float p0n = xpp[(size_t)tn * (BATCH * HID)];
        float p1n = xpp[(size_t)tn * (BATCH * HID) + HID];

        // k-loop: 32 h-quads x 4 batches (all loads warp-uniform broadcasts)
#pragma unroll
        for (int u = 0; u < 32; u++) {
            ulonglong2 h0 = *(const ulonglong2*)&hsm[0][u * 4];
            ulonglong2 h1 = *(const ulonglong2*)&hsm[1][u * 4];
            ulonglong2 h2 = *(const ulonglong2*)&hsm[2][u * 4];
            ulonglong2 h3 = *(const ulonglong2*)&hsm[3][u * 4];
            ffma2(a00, h0.x, wreg[2 * u]);
            ffma2(a01, h0.y, wreg[2 * u + 1]);
            ffma2(a10, h1.x, wreg[2 * u]);
            ffma2(a11, h1.y, wreg[2 * u + 1]);
            ffma2(a20, h2.x, wreg[2 * u]);
            ffma2(a21, h2.y, wreg[2 * u + 1]);
            ffma2(a30, h3.x, wreg[2 * u]);
            ffma2(a31, h3.y, wreg[2 * u + 1]);
        }

        // collapse to 4 partial scalars
        fadd2(a00, a01);
        fadd2(a10, a11);
        fadd2(a20, a21);
        fadd2(a30, a31);
        float lo, hi;
        f32x2_unpack(a00, lo, hi); float s0 = lo + hi;
        f32x2_unpack(a10, lo, hi); float s1 = lo + hi;
        f32x2_unpack(a20, lo, hi); float s2 = lo + hi;
        f32x2_unpack(a30, lo, hi); float s3 = lo + hi;
        unsigned long long P01 = f32x2_pack(s0, s1);
        unsigned long long P23 = f32x2_pack(s2, s3);

        // publish partials
        if (is_local) {
            *(unsigned long long*)&X[par][0][jl_local][0] = P01;
            *(unsigned long long*)&X[par][0][jl_local][2] = P23;
        } else {
            uint32_t la = smem_u32(&X[par][1][jl_remote][0]);
            uint32_t ra = mapa_peer(la, rank ^ 1);
            st_cluster_u64(ra, P01);
            st_cluster_u64(ra + 8, P23);
        }
        __syncthreads();
        if (tid == 0) {
            asm volatile(
                "mbarrier.arrive.release.cluster.shared::cluster.b64 _, [%0];"
                :: "r"(mbar_peer) : "memory");
        }
        // wait for peer's partials (parity = t&1), acquire at cluster scope
        {
            asm volatile(
                "{\n\t.reg .pred P1;\n\t"
                "WL_%=:\n\t"
                "mbarrier.try_wait.parity.acquire.cluster.shared::cta.b64 P1, [%0], %1, 0x989680;\n\t"
                "@P1 bra.uni WD_%=;\n\t"
                "bra.uni WL_%=;\n\t"
                "WD_%=:\n\t}" :: "r"(mymbar), "r"((uint32_t)par) : "memory");
        }

        // finalize: 2 outputs (col kb+fcol, batches bb, bb+1)
        float2 v0 = *(const float2*)&X[par][0][fcol][bb];
        float2 v1 = *(const float2*)&X[par][1][fcol][bb];
        h0v = tanhf(v0.x + v1.x + p0);
        h1v = tanhf(v0.y + v1.y + p1);
        hsm[bb][fcol]     = h0v;
        hsm[bb + 1][fcol] = h1v;
        p0 = p0n;
        p1 = p1n;
        __syncthreads();
    }

    g_hfinal[(size_t)(b0c + bb) * HID + kb + fcol]     = h0v;
    g_hfinal[(size_t)(b0c + bb + 1) * HID + kb + fcol] = h1v;

    // cluster-wide exit sync: no CTA may exit while peer still sends arrives
    asm volatile("barrier.cluster.arrive.aligned;" ::: "memory");
    asm volatile("barrier.cluster.wait.aligned;" ::: "memory");
}

// ---------------------------------------------------------------------------
// Kernel 3: classifier head (tiny)
// ---------------------------------------------------------------------------
__global__ __launch_bounds__(128)
void rnn_head_kernel(const float* __restrict__ fcw,
                     const float* __restrict__ fcb,
                     float* __restrict__ out) {
    __shared__ float hs[HID];
    __shared__ float part[8][OUT_DIM];
    const int b = blockIdx.x;
    const int tid = threadIdx.x;

    hs[tid]       = g_hfinal[(size_t)b * HID + tid];
    hs[tid + 128] = g_hfinal[(size_t)b * HID + tid + 128];
    __syncthreads();

    const int o   = tid & 15;
    const int seg = tid >> 4;
    float s = 0.f;
#pragma unroll
    for (int jj = 0; jj < 32; jj++) {
        int j = seg * 32 + jj;
        s += hs[j] * fcw[o * HID + j];
    }
    part[seg][o] = s;
    __syncthreads();
    if (tid < OUT_DIM) {
        float r = fcb[tid];
#pragma unroll
        for (int sg = 0; sg < 8; sg++) r += part[sg][tid];
        out[b * OUT_DIM + tid] = r;
    }
}

// ---------------------------------------------------------------------------
extern "C" void kernel_launch(void* const* d_in, const int* in_sizes, int n_in,
                              void* d_out, int out_size) {
    const float* x   = (const float*)d_in[0];
    const float* Wih = (const float*)d_in[1];
    const float* Whh = (const float*)d_in[2];
    const float* bh  = (const float*)d_in[3];
    const float* fcw = (const float*)d_in[4];
    const float* fcb = (const float*)d_in[5];
    float* out = (float*)d_out;

    // 0) bf16 hi/lo splits of W_ih^T and x
    prep_w_kernel<<<256, 256>>>(Wih);
    prep_x_kernel<<<131072, 256>>>(x);

    // 1) input projection GEMM on tensor cores (mma.sync) -> g_xp
    cudaFuncSetAttribute(gemm_xp_mma_kernel,
                         cudaFuncAttributeMaxDynamicSharedMemorySize, GSMEM);
    gemm_xp_mma_kernel<<<(BATCH * T_STEPS) / 128, 512, GSMEM>>>(bh);

    // 2) persistent recurrence: 64 clusters x 2 CTAs, W in registers
    rnn_recurrence_kernel<<<128, 256>>>(Whh);

    // 3) classifier head
    rnn_head_kernel<<<BATCH, 128>>>(fcw, fcb, out);
}

// round 11
// speedup vs baseline: 1.0167x; 1.0167x over previous
#include <cuda_runtime.h>
#include <cuda_bf16.h>
#include <math.h>
#include <stdint.h>

// Problem constants (fixed shapes)
#define T_STEPS 2048
#define BATCH   256
#define HID     256
#define OUT_DIM 16

// Scratch (device globals: allocation-free kernel_launch)
__device__ float g_xp[134217728];          // [T][B][H] fp32, 512 MB
__device__ float g_hfinal[BATCH * HID];
__device__ __nv_bfloat16 g_xhi[134217728]; // x hi split, 256 MB
__device__ __nv_bfloat16 g_xlo[134217728]; // x lo split, 256 MB
__device__ __nv_bfloat16 g_WThi[65536];    // W_ih^T hi: [n][k]
__device__ __nv_bfloat16 g_WTlo[65536];    // W_ih^T lo: [n][k]

// ---------------------------------------------------------------------------
// helpers
// ---------------------------------------------------------------------------
__device__ __forceinline__ uint32_t smem_u32(const void* p) {
    uint32_t a;
    asm("{ .reg .u64 t; cvta.to.shared.u64 t, %1; cvt.u32.u64 %0, t; }"
        : "=r"(a) : "l"(p));
    return a;
}
__device__ __forceinline__ void cp16(uint32_t dst, const void* src) {
    asm volatile("cp.async.cg.shared.global [%0], [%1], 16;"
                 :: "r"(dst), "l"(src) : "memory");
}
__device__ __forceinline__ void ldsm_x4(uint32_t* r, uint32_t addr) {
    asm volatile("ldmatrix.sync.aligned.m8n8.x4.shared.b16 {%0,%1,%2,%3}, [%4];"
                 : "=r"(r[0]), "=r"(r[1]), "=r"(r[2]), "=r"(r[3]) : "r"(addr));
}
__device__ __forceinline__ void ldsm_x2(uint32_t* r, uint32_t addr) {
    asm volatile("ldmatrix.sync.aligned.m8n8.x2.shared.b16 {%0,%1}, [%2];"
                 : "=r"(r[0]), "=r"(r[1]) : "r"(addr));
}
__device__ __forceinline__ void mma_bf16(float* c, const uint32_t* a, const uint32_t* b) {
    asm volatile(
        "mma.sync.aligned.m16n8k16.row.col.f32.bf16.bf16.f32 "
        "{%0,%1,%2,%3}, {%4,%5,%6,%7}, {%8,%9}, {%0,%1,%2,%3};"
        : "+f"(c[0]), "+f"(c[1]), "+f"(c[2]), "+f"(c[3])
        : "r"(a[0]), "r"(a[1]), "r"(a[2]), "r"(a[3]), "r"(b[0]), "r"(b[1]));
}

// f32x2 helpers
__device__ __forceinline__ unsigned long long f32x2_pack(float x, float y) {
    unsigned long long r;
    asm("mov.b64 %0, {%1, %2};" : "=l"(r) : "r"(__float_as_uint(x)), "r"(__float_as_uint(y)));
    return r;
}
__device__ __forceinline__ void f32x2_unpack(unsigned long long v, float& x, float& y) {
    unsigned int lo, hi;
    asm("mov.b64 {%0, %1}, %2;" : "=r"(lo), "=r"(hi) : "l"(v));
    x = __uint_as_float(lo);
    y = __uint_as_float(hi);
}
__device__ __forceinline__ void ffma2(unsigned long long& acc,
                                      unsigned long long a, unsigned long long b) {
    asm("fma.rn.f32x2 %0, %1, %2, %0;" : "+l"(acc) : "l"(a), "l"(b));
}
__device__ __forceinline__ void fadd2(unsigned long long& acc, unsigned long long b) {
    asm("add.rn.f32x2 %0, %0, %1;" : "+l"(acc) : "l"(b));
}

// ---------------------------------------------------------------------------
// Kernel 0a: W_ih [k][n] -> transposed bf16 hi/lo [n][k]
// ---------------------------------------------------------------------------
__global__ __launch_bounds__(256)
void prep_w_kernel(const float* __restrict__ Wih) {
    int n = blockIdx.x;
    int k = threadIdx.x;
    float w = Wih[k * 256 + n];
    __nv_bfloat16 hi = __float2bfloat16(w);
    float lof = w - __bfloat162float(hi);
    g_WThi[n * 256 + k] = hi;
    g_WTlo[n * 256 + k] = __float2bfloat16(lof);
}

// ---------------------------------------------------------------------------
// Kernel 0b: x fp32 -> bf16 hi/lo splits (streaming)
// ---------------------------------------------------------------------------
__global__ __launch_bounds__(256)
void prep_x_kernel(const float* __restrict__ x) {
    size_t i = ((size_t)blockIdx.x * 256 + threadIdx.x) * 4;
    float4 f = *(const float4*)&x[i];
    __nv_bfloat162 h0 = __float22bfloat162_rn(make_float2(f.x, f.y));
    __nv_bfloat162 h1 = __float22bfloat162_rn(make_float2(f.z, f.w));
    float2 l0 = make_float2(f.x - __bfloat162float(h0.x), f.y - __bfloat162float(h0.y));
    float2 l1 = make_float2(f.z - __bfloat162float(h1.x), f.w - __bfloat162float(h1.y));
    __nv_bfloat162 lo0 = __float22bfloat162_rn(l0);
    __nv_bfloat162 lo1 = __float22bfloat162_rn(l1);
    uint2 hv, lv;
    hv.x = *(uint32_t*)&h0; hv.y = *(uint32_t*)&h1;
    lv.x = *(uint32_t*)&lo0; lv.y = *(uint32_t*)&lo1;
    *(uint2*)&g_xhi[i] = hv;
    *(uint2*)&g_xlo[i] = lv;
}

// ---------------------------------------------------------------------------
// Kernel 1: mma.sync bf16-split GEMM (unchanged from R5 passing version)
// ---------------------------------------------------------------------------
#define PADROW   40
#define AHI_OFF  0
#define ALO_OFF  10240
#define BHI_OFF  20480
#define BLO_OFF  40960
#define STAGE_B  61440
#define GSMEM    (2 * STAGE_B)

__global__ __launch_bounds__(512, 1)
void gemm_xp_mma_kernel(const float* __restrict__ bh) {
    extern __shared__ __align__(16) char dsm[];
    __shared__ float bias_s[256];

    const int tid = threadIdx.x;
    const int wid = tid >> 5;
    const int lid = tid & 31;
    const int wm  = wid & 1;
    const int wn  = wid >> 1;
    const uint32_t sb = smem_u32(dsm);

    if (tid < 256) bias_s[tid] = bh[tid];

    const size_t r0 = (size_t)blockIdx.x * 128;

    auto fill = [&](int s, int kt) {
        uint32_t base = sb + s * STAGE_B;
        {
            int c = tid;
            int row = c >> 2, q = c & 3;
            size_t ga = (r0 + row) * 256 + kt + q * 8;
            uint32_t d = base + row * (PADROW * 2) + q * 16;
            cp16(d + AHI_OFF, g_xhi + ga);
            cp16(d + ALO_OFF, g_xlo + ga);
        }
#pragma unroll
        for (int i = 0; i < 2; i++) {
            int c = tid + i * 512;
            int row = c >> 2, q = c & 3;
            size_t gb = (size_t)row * 256 + kt + q * 8;
            uint32_t d = base + row * (PADROW * 2) + q * 16;
            cp16(d + BHI_OFF, g_WThi + gb);
            cp16(d + BLO_OFF, g_WTlo + gb);
        }
    };

    float acc[4][4][4];
#pragma unroll
    for (int mi = 0; mi < 4; mi++)
#pragma unroll
        for (int ni = 0; ni < 4; ni++)
#pragma unroll
            for (int e = 0; e < 4; e++) acc[mi][ni][e] = 0.f;

    fill(0, 0);
    asm volatile("cp.async.commit_group;" ::: "memory");
    fill(1, 32);
    asm volatile("cp.async.commit_group;" ::: "memory");

    const int arow  = wm * 64 + (lid & 15);
    const int acolb = (lid >> 4) * 16;
    const int bnrow = wn * 32 + (lid & 7);
    const int bkoff = ((lid >> 3) & 1) * 16;

    for (int it = 0; it < 8; it++) {
        asm volatile("cp.async.wait_group 1;" ::: "memory");
        __syncthreads();

        uint32_t As = sb + (it & 1) * STAGE_B;
        uint32_t Bs = As + BHI_OFF;

#pragma unroll
        for (int k16 = 0; k16 < 2; k16++) {
            uint32_t ahi[4][4], alo[4][4];
#pragma unroll
            for (int mi = 0; mi < 4; mi++) {
                uint32_t a = As + (arow + mi * 16) * (PADROW * 2) + k16 * 32 + acolb;
                ldsm_x4(ahi[mi], a + AHI_OFF);
                ldsm_x4(alo[mi], a + ALO_OFF);
            }
#pragma unroll
            for (int ni = 0; ni < 4; ni++) {
                uint32_t bhi[2], blo[2];
                uint32_t ba = Bs + (bnrow + ni * 8) * (PADROW * 2) + k16 * 32 + bkoff;
                ldsm_x2(bhi, ba);
                ldsm_x2(blo, ba + (BLO_OFF - BHI_OFF));
#pragma unroll
                for (int mi = 0; mi < 4; mi++) {
                    mma_bf16(acc[mi][ni], ahi[mi], bhi);
                    mma_bf16(acc[mi][ni], alo[mi], bhi);
                    mma_bf16(acc[mi][ni], ahi[mi], blo);
                }
            }
        }
        __syncthreads();
        if (it + 2 < 8) fill(it & 1, (it + 2) * 32);
        asm volatile("cp.async.commit_group;" ::: "memory");
    }

#pragma unroll
    for (int mi = 0; mi < 4; mi++) {
#pragma unroll
        for (int ni = 0; ni < 4; ni++) {
            int m = wm * 64 + mi * 16 + (lid >> 2);
            int n = wn * 32 + ni * 8 + (lid & 3) * 2;
            float b0 = bias_s[n], b1 = bias_s[n + 1];
            {
                size_t r = r0 + m;
                int t = (int)(r & 2047), b = (int)(r >> 11);
                float2 v = make_float2(acc[mi][ni][0] + b0, acc[mi][ni][1] + b1);
                *(float2*)&g_xp[((size_t)t * BATCH + b) * HID + n] = v;
            }
            {
                size_t r = r0 + m + 8;
                int t = (int)(r & 2047), b = (int)(r >> 11);
                float2 v = make_float2(acc[mi][ni][2] + b0, acc[mi][ni][3] + b1);
                *(float2*)&g_xp[((size_t)t * BATCH + b) * HID + n] = v;
            }
        }
    }
}

// ---------------------------------------------------------------------------
// Kernel 2: full-K recurrence, 192 W-rows in registers, ONE barrier/step.
// 128 CTAs x 256 threads. Thread j owns column j, both batches, all k:
//   - W rows [0, 192)  : registers (96 u64 k-pairs)
//   - W rows [192, 256): smem quads [group][j][4] (16 groups)
// h double-buffered by step parity: write buffer (t+1)&1 while reading t&1,
// so a single __syncthreads per step suffices. All h loads are 16B warp
// broadcasts; no exchange, no shfl, no cluster.
// smem: W 16 * 4096 = 65536 | h 2 par x 2 batch x 1024B = 4096 -> 69632.
// ---------------------------------------------------------------------------
#define RREGP    96                 // u64 W k-pairs in regs (rows 0..191)
#define RGROUPS  16                 // smem quad groups (rows 192..255)
#define RW_BYTES (RGROUPS * 4096)   // 65536
#define RH_OFF   RW_BYTES
#define RSMEM    (RW_BYTES + 4096)

__global__ __launch_bounds__(256, 1)
void rnn_recurrence_kernel(const float* __restrict__ W_hh) {
    extern __shared__ __align__(16) char sm[];

    const int j  = threadIdx.x;
    const int b0 = blockIdx.x * 2;

    // --- fill W smem quads: group g -> rows 192 + 4g .. +3, layout [g][j][4] ---
    for (int e = j; e < RGROUPS * 256; e += 256) {
        int g  = e >> 8;
        int jj = e & 255;
        int row = 192 + 4 * g;
        float4 v;
        v.x = W_hh[(row + 0) * 256 + jj];
        v.y = W_hh[(row + 1) * 256 + jj];
        v.z = W_hh[(row + 2) * 256 + jj];
        v.w = W_hh[(row + 3) * 256 + jj];
        *(float4*)(sm + g * 4096 + jj * 16) = v;
    }

    // --- W rows [0, 192) of column j -> 96 u64 k-pair registers ---
    unsigned long long wreg[RREGP];
#pragma unroll
    for (int r = 0; r < RREGP; r++)
        wreg[r] = f32x2_pack(W_hh[(2 * r) * 256 + j],
                             W_hh[(2 * r + 1) * 256 + j]);

    // --- zero h parity-0 buffer: [batch][256] ---
    ((float*)(sm + RH_OFF))[j]       = 0.f;
    ((float*)(sm + RH_OFF))[256 + j] = 0.f;
    __syncthreads();

    const float* xp = g_xp + (size_t)b0 * HID + j;
    float p0 = xp[0];
    float p1 = xp[HID];
    float h0v = 0.f, h1v = 0.f;

    for (int t = 0; t < T_STEPS; t++) {
        const char* hb  = sm + RH_OFF + (t & 1) * 2048;
        const char* h0p = hb;          // batch0 h[256]
        const char* h1p = hb + 1024;   // batch1 h[256]

        // 4 accumulator chains
        unsigned long long a0x = 0, a0y = 0, a1x = 0, a1y = 0;

        int tn = (t + 1 < T_STEPS) ? (t + 1) : t;
        float p0n = xp[(size_t)tn * (BATCH * HID)];
        float p1n = xp[(size_t)tn * (BATCH * HID) + HID];

        // register-W part: k in [0,192), 48 h-chunks of 16B per batch
#pragma unroll
        for (int u = 0; u < 48; u++) {
            ulonglong2 h0 = *(const ulonglong2*)(h0p + u * 16);
            ulonglong2 h1 = *(const ulonglong2*)(h1p + u * 16);
            ffma2(a0x, h0.x, wreg[2 * u]);
            ffma2(a0y, h0.y, wreg[2 * u + 1]);
            ffma2(a1x, h1.x, wreg[2 * u]);
            ffma2(a1y, h1.y, wreg[2 * u + 1]);
        }
        // smem-W part: k in [192,256), 16 quad groups
#pragma unroll
        for (int g = 0; g < RGROUPS; g++) {
            ulonglong2 w  = *(const ulonglong2*)(sm + g * 4096 + j * 16);
            ulonglong2 h0 = *(const ulonglong2*)(h0p + 768 + g * 16);
            ulonglong2 h1 = *(const ulonglong2*)(h1p + 768 + g * 16);
            ffma2(a0x, h0.x, w.x);
            ffma2(a0y, h0.y, w.y);
            ffma2(a1x, h1.x, w.x);
            ffma2(a1y, h1.y, w.y);
        }

        fadd2(a0x, a0y);
        fadd2(a1x, a1y);
        float lo, hi;
        f32x2_unpack(a0x, lo, hi);
        h0v = tanhf(lo + hi + p0);
        f32x2_unpack(a1x, lo, hi);
        h1v = tanhf(lo + hi + p1);
        p0 = p0n;
        p1 = p1n;

        // publish into the other parity buffer; single barrier per step
        float* hn = (float*)(sm + RH_OFF + ((t + 1) & 1) * 2048);
        hn[j]       = h0v;
        hn[256 + j] = h1v;
        __syncthreads();
    }

    g_hfinal[(size_t)b0 * HID + j]       = h0v;
    g_hfinal[(size_t)(b0 + 1) * HID + j] = h1v;
}

// ---------------------------------------------------------------------------
// Kernel 3: classifier head (tiny)
// ---------------------------------------------------------------------------
__global__ __launch_bounds__(128)
void rnn_head_kernel(const float* __restrict__ fcw,
                     const float* __restrict__ fcb,
                     float* __restrict__ out) {
    __shared__ float hs[HID];
    __shared__ float part[8][OUT_DIM];
    const int b = blockIdx.x;
    const int tid = threadIdx.x;

    hs[tid]       = g_hfinal[(size_t)b * HID + tid];
    hs[tid + 128] = g_hfinal[(size_t)b * HID + tid + 128];
    __syncthreads();

    const int o   = tid & 15;
    const int seg = tid >> 4;
    float s = 0.f;
#pragma unroll
    for (int jj = 0; jj < 32; jj++) {
        int j = seg * 32 + jj;
        s += hs[j] * fcw[o * HID + j];
    }
    part[seg][o] = s;
    __syncthreads();
    if (tid < OUT_DIM) {
        float r = fcb[tid];
#pragma unroll
        for (int sg = 0; sg < 8; sg++) r += part[sg][tid];
        out[b * OUT_DIM + tid] = r;
    }
}

// ---------------------------------------------------------------------------
extern "C" void kernel_launch(void* const* d_in, const int* in_sizes, int n_in,
                              void* d_out, int out_size) {
    const float* x   = (const float*)d_in[0];
    const float* Wih = (const float*)d_in[1];
    const float* Whh = (const float*)d_in[2];
    const float* bh  = (const float*)d_in[3];
    const float* fcw = (const float*)d_in[4];
    const float* fcb = (const float*)d_in[5];
    float* out = (float*)d_out;

    // 0) bf16 hi/lo splits of W_ih^T and x
    prep_w_kernel<<<256, 256>>>(Wih);
    prep_x_kernel<<<131072, 256>>>(x);

    // 1) input projection GEMM on tensor cores (mma.sync) -> g_xp
    cudaFuncSetAttribute(gemm_xp_mma_kernel,
                         cudaFuncAttributeMaxDynamicSharedMemorySize, GSMEM);
    gemm_xp_mma_kernel<<<(BATCH * T_STEPS) / 128, 512, GSMEM>>>(bh);

    // 2) persistent recurrence: full-K, 192 W-rows in regs, 1 barrier/step
    cudaFuncSetAttribute(rnn_recurrence_kernel,
                         cudaFuncAttributeMaxDynamicSharedMemorySize, RSMEM);
    rnn_recurrence_kernel<<<BATCH / 2, 256, RSMEM>>>(Whh);

    // 3) classifier head
    rnn_head_kernel<<<BATCH, 128>>>(fcw, fcb, out);
}